// round 2
// baseline (speedup 1.0000x reference)
#include <cuda_runtime.h>
#include <cmath>
#include <cstring>
#include <complex>
#include <cstdlib>

#define NTHREADS 256
#define TB 64            // batch tile
#define UVC 32           // (u,v) chunk size
#define SXP 65           // padded batch stride for staged x tiles
#define SX_ELEMS (192 * SXP)
#define CG_CAP 256

struct PathP {
    int m1, m2, L1, L2, off1, off2, woff, m2shift;
    int cg_beg[6];
};
struct Params {
    int npaths, ncg;
    float coeff;
    PathP path[4];
    int   cg_pack[CG_CAP];   // i | (j<<4)
    float cg_val[CG_CAP];
};
struct AllParams { Params p[3]; };

// smem layout (floats): [cg float2 x CG_CAP][sx1 192*65][sx2 192*65][sP 32*5*64][sW 32*128]
#define SMEM_BYTES (8 * CG_CAP + 4 * (2 * SX_ELEMS + UVC * 5 * TB + UVC * 128))

// ---------------------------- device ---------------------------------------

__device__ __forceinline__ void ffma2(unsigned long long& d, unsigned long long a,
                                      unsigned long long b) {
    asm("fma.rn.f32x2 %0, %1, %2, %0;" : "+l"(d) : "l"(a), "l"(b));
}
__device__ __forceinline__ unsigned long long bcast2(unsigned u) {
    unsigned long long r;
    asm("mov.b64 %0, {%1, %1};" : "=l"(r) : "r"(u));
    return r;
}

template<int M3, int L3, int OFF3>
__device__ __forceinline__ void run_i3(const float* __restrict__ x1,
                                       const float* __restrict__ x2,
                                       const float* __restrict__ wgt,
                                       float* __restrict__ out,
                                       const Params& P, int tile)
{
    extern __shared__ float smem[];
    float2* scg = (float2*)smem;
    float* sx1 = smem + 2 * CG_CAP;
    float* sx2 = sx1 + SX_ELEMS;
    float* sP  = sx2 + SX_ELEMS;
    float* sW  = sP + UVC * 5 * TB;

    const int tid = threadIdx.x;
    const int bt  = tid >> 5;     // 0..7: batch group of 8
    const int wt  = tid & 31;     // 0..31: w lane
    constexpr int R = M3 / 32;

    // stage CG tables to smem (avoid LDC rt=8 floor in P-compute)
    for (int e = tid; e < P.ncg; e += NTHREADS)
        scg[e] = make_float2(P.cg_val[e], __int_as_float(P.cg_pack[e]));

    unsigned long long acc[4][R][L3];
#pragma unroll
    for (int a = 0; a < 4; ++a)
#pragma unroll
        for (int r = 0; r < R; ++r)
#pragma unroll
            for (int k = 0; k < L3; ++k) acc[a][r][k] = 0ull;

    for (int p = 0; p < P.npaths; ++p) {
        const PathP& pp = P.path[p];
        const int C1q = (pp.m1 * pp.L1) >> 2;     // float4s per batch row, block 1
        const int C2q = (pp.m2 * pp.L2) >> 2;
        const float* gx1 = x1 + (size_t)tile * TB * 480 + pp.off1;
        const float* gx2 = x2 + (size_t)tile * TB * 480 + pp.off2;

        __syncthreads();   // previous GEMM / cg copy done before overwriting sx
        for (int idx = tid; idx < TB * C1q; idx += NTHREADS) {
            int b = idx / C1q, qq = idx - b * C1q;
            float4 v = *(const float4*)(gx1 + b * 480 + (qq << 2));
            int c = qq << 2;
            sx1[(c + 0) * SXP + b] = v.x; sx1[(c + 1) * SXP + b] = v.y;
            sx1[(c + 2) * SXP + b] = v.z; sx1[(c + 3) * SXP + b] = v.w;
        }
        for (int idx = tid; idx < TB * C2q; idx += NTHREADS) {
            int b = idx / C2q, qq = idx - b * C2q;
            float4 v = *(const float4*)(gx2 + b * 480 + (qq << 2));
            int c = qq << 2;
            sx2[(c + 0) * SXP + b] = v.x; sx2[(c + 1) * SXP + b] = v.y;
            sx2[(c + 2) * SXP + b] = v.z; sx2[(c + 3) * SXP + b] = v.w;
        }
        __syncthreads();

        const int KUV   = pp.m1 * pp.m2;
        const int vmask = pp.m2 - 1;
        const int msh   = pp.m2shift;

        for (int uv0 = 0; uv0 < KUV; uv0 += UVC) {
            // stage W chunk [UVC][M3] (contiguous)
            const float4* gw = (const float4*)(wgt + (size_t)pp.woff + (size_t)uv0 * M3);
            constexpr int WIT = UVC * M3 / 4 / NTHREADS;
#pragma unroll
            for (int it = 0; it < WIT; ++it)
                ((float4*)sW)[it * NTHREADS + tid] = gw[it * NTHREADS + tid];

            // compute P chunk [UVC][L3][TB]
            for (int it = 0; it < UVC * TB / NTHREADS; ++it) {
                int idx = it * NTHREADS + tid;
                int uvc = idx >> 6;           // / TB
                int b   = idx & (TB - 1);
                int uv  = uv0 + uvc;
                const float* px1 = sx1 + ((uv >> msh) * pp.L1) * SXP + b;
                const float* px2 = sx2 + ((uv & vmask) * pp.L2) * SXP + b;
#pragma unroll
                for (int k = 0; k < L3; ++k) {
                    float s = 0.f;
                    const int e1 = pp.cg_beg[k + 1];
                    for (int e = pp.cg_beg[k]; e < e1; ++e) {
                        float2 ce = scg[e];
                        int pk = __float_as_int(ce.y);
                        s += ce.x * px1[(pk & 15) * SXP] * px2[(pk >> 4) * SXP];
                    }
                    sP[(uvc * L3 + k) * TB + b] = s;
                }
            }
            __syncthreads();

            // register-tile GEMM, batch pairs packed in f32x2
#pragma unroll 8
            for (int uvc = 0; uvc < UVC; ++uvc) {
                unsigned long long wr[R];
#pragma unroll
                for (int r = 0; r < R; ++r)
                    wr[r] = bcast2(__float_as_uint(sW[uvc * M3 + wt + 32 * r]));
#pragma unroll
                for (int k = 0; k < L3; ++k) {
                    const float* sPk = sP + (uvc * L3 + k) * TB + (bt << 3);
                    ulonglong2 qa = *(const ulonglong2*)(sPk);
                    ulonglong2 qb = *(const ulonglong2*)(sPk + 4);
#pragma unroll
                    for (int r = 0; r < R; ++r) {
                        ffma2(acc[0][r][k], qa.x, wr[r]);
                        ffma2(acc[1][r][k], qa.y, wr[r]);
                        ffma2(acc[2][r][k], qb.x, wr[r]);
                        ffma2(acc[3][r][k], qb.y, wr[r]);
                    }
                }
            }
            __syncthreads();
        }
    }

    const float coeff = P.coeff;
#pragma unroll
    for (int pb = 0; pb < 4; ++pb) {
        size_t b0 = (size_t)tile * TB + (bt << 3) + pb * 2;
        float* o0 = out + b0 * 480 + OFF3;
#pragma unroll
        for (int r = 0; r < R; ++r)
#pragma unroll
            for (int k = 0; k < L3; ++k) {
                unsigned long long v = acc[pb][r][k];
                int oc = (wt + 32 * r) * L3 + k;
                o0[oc]       = coeff * __uint_as_float((unsigned)(v & 0xffffffffull));
                o0[480 + oc] = coeff * __uint_as_float((unsigned)(v >> 32));
            }
    }
}

__global__ void __launch_bounds__(NTHREADS, 1)
tp_kernel(const float* __restrict__ x1, const float* __restrict__ x2,
          const float* __restrict__ wgt, float* __restrict__ out, AllParams ap)
{
    const int tile = blockIdx.y;
    if (blockIdx.x == 0)      run_i3<128, 1, 0>  (x1, x2, wgt, out, ap.p[0], tile);
    else if (blockIdx.x == 1) run_i3<64,  3, 128>(x1, x2, wgt, out, ap.p[1], tile);
    else                      run_i3<32,  5, 320>(x1, x2, wgt, out, ap.p[2], tile);
}

// ---------------------------- host: CG construction -------------------------

typedef std::complex<double> cpx;

static double fct(int n) { double r = 1.0; for (int i = 2; i <= n; ++i) r *= i; return r; }

static void change_basis(int l, cpx q[5][5]) {
    for (int a = 0; a < 5; ++a) for (int b = 0; b < 5; ++b) q[a][b] = cpx(0, 0);
    const double s2 = 1.0 / std::sqrt(2.0);
    for (int m = -l; m < 0; ++m) {
        q[l + m][l - m] = cpx(s2, 0);     // q[l+m, l+|m|]
        q[l + m][l + m] = cpx(0, -s2);    // q[l+m, l-|m|]
    }
    q[l][l] = cpx(1, 0);
    for (int m = 1; m <= l; ++m) {
        double sg = (m & 1) ? -1.0 : 1.0;
        q[l + m][l + m] = cpx(sg * s2, 0);
        q[l + m][l - m] = cpx(0, sg * s2);
    }
    cpx ph(1, 0);
    for (int t = 0; t < l; ++t) ph *= cpx(0, -1);   // (-1j)^l
    for (int a = 0; a < 2 * l + 1; ++a) for (int b = 0; b < 2 * l + 1; ++b) q[a][b] *= ph;
}

static void real_cg(int l1, int l2, int l3, float outc[5][5][5]) {
    cpx Q1[5][5], Q2[5][5], Q3[5][5];
    change_basis(l1, Q1); change_basis(l2, Q2); change_basis(l3, Q3);
    double C[5][5][5];
    memset(C, 0, sizeof(C));
    for (int m1 = -l1; m1 <= l1; ++m1)
        for (int m2 = -l2; m2 <= l2; ++m2) {
            int m3 = m1 + m2;
            if (m3 < -l3 || m3 > l3) continue;
            double pref = std::sqrt((2.0 * l3 + 1.0)
                * fct(l3 + l1 - l2) * fct(l3 - l1 + l2) * fct(l1 + l2 - l3) / fct(l1 + l2 + l3 + 1)
                * fct(l3 + m3) * fct(l3 - m3) * fct(l1 - m1) * fct(l1 + m1)
                * fct(l2 - m2) * fct(l2 + m2));
            double s = 0.0;
            for (int k = 0; k <= l1 + l2 - l3; ++k) {
                if (l1 - m1 - k < 0 || l2 + m2 - k < 0 ||
                    l3 - l2 + m1 + k < 0 || l3 - l1 - m2 + k < 0) continue;
                double d = fct(k) * fct(l1 + l2 - l3 - k) * fct(l1 - m1 - k)
                         * fct(l2 + m2 - k) * fct(l3 - l2 + m1 + k) * fct(l3 - l1 - m2 + k);
                s += ((k & 1) ? -1.0 : 1.0) / d;
            }
            C[l1 + m1][l2 + m2][l3 + m3] = pref * s;
        }
    int n1 = 2 * l1 + 1, n2 = 2 * l2 + 1, n3 = 2 * l3 + 1;
    double Rr[5][5][5], nrm = 0.0;
    for (int j = 0; j < n1; ++j)
        for (int lb = 0; lb < n2; ++lb)
            for (int nn = 0; nn < n3; ++nn) {
                cpx a(0, 0);
                for (int i = 0; i < n1; ++i)
                    for (int kk = 0; kk < n2; ++kk)
                        for (int m = 0; m < n3; ++m)
                            if (C[i][kk][m] != 0.0)
                                a += Q1[i][j] * Q2[kk][lb] * Q3[m][nn] * C[i][kk][m];
                Rr[j][lb][nn] = a.real();
                nrm += a.real() * a.real();
            }
    nrm = std::sqrt(nrm);
    for (int j = 0; j < 5; ++j) for (int lb = 0; lb < 5; ++lb) for (int nn = 0; nn < 5; ++nn)
        outc[j][lb][nn] = (j < n1 && lb < n2 && nn < n3) ? (float)(Rr[j][lb][nn] / nrm) : 0.f;
}

static void build_params(AllParams& ap) {
    memset(&ap, 0, sizeof(ap));
    const int M_[3] = {128, 64, 32}, L_[3] = {0, 1, 2}, P_[3] = {1, -1, 1},
              O_[3] = {0, 128, 320};
    long long fan[3] = {0, 0, 0};
    int woff = 0;
    for (int i1 = 0; i1 < 3; ++i1)
        for (int i2 = 0; i2 < 3; ++i2)
            for (int i3 = 0; i3 < 3; ++i3) {
                int l1 = L_[i1], l2 = L_[i2], l3 = L_[i3];
                if (P_[i1] * P_[i2] != P_[i3]) continue;
                int lo = abs(l1 - l2);
                if (l3 < lo || l3 > l1 + l2) continue;
                float C[5][5][5];
                real_cg(l1, l2, l3, C);
                Params& pr = ap.p[i3];
                PathP& pp = pr.path[pr.npaths++];
                pp.m1 = M_[i1]; pp.m2 = M_[i2];
                pp.L1 = 2 * l1 + 1; pp.L2 = 2 * l2 + 1;
                pp.off1 = O_[i1]; pp.off2 = O_[i2];
                pp.woff = woff;
                pp.m2shift = (pp.m2 == 128) ? 7 : (pp.m2 == 64) ? 6 : 5;
                int L3 = 2 * l3 + 1;
                for (int k = 0; k < L3; ++k) {
                    pp.cg_beg[k] = pr.ncg;
                    for (int i = 0; i < pp.L1; ++i)
                        for (int j = 0; j < pp.L2; ++j) {
                            float v = C[i][j][k];
                            if (fabsf(v) > 1e-12f) {
                                pr.cg_pack[pr.ncg] = i | (j << 4);
                                pr.cg_val[pr.ncg] = v;
                                pr.ncg++;
                            }
                        }
                }
                pp.cg_beg[L3] = pr.ncg;
                woff += pp.m1 * pp.m2 * M_[i3];
                fan[i3] += (long long)pp.m1 * pp.m2;
            }
    for (int i3 = 0; i3 < 3; ++i3)
        ap.p[i3].coeff = std::sqrt((double)(2 * L_[i3] + 1) / (double)fan[i3]);
}

// ---------------------------- entry -----------------------------------------

extern "C" void kernel_launch(void* const* d_in, const int* in_sizes, int n_in,
                              void* d_out, int out_size) {
    AllParams ap;
    build_params(ap);
    cudaFuncSetAttribute(tp_kernel, cudaFuncAttributeMaxDynamicSharedMemorySize, SMEM_BYTES);
    tp_kernel<<<dim3(3, 128), NTHREADS, SMEM_BYTES>>>(
        (const float*)d_in[0], (const float*)d_in[1], (const float*)d_in[2],
        (float*)d_out, ap);
}